// round 14
// baseline (speedup 1.0000x reference)
#include <cuda_runtime.h>
#include <cstdint>

#define BATCH 32
#define NKVH 8
#define HIDDEN 4096
#define NQKV 6144
#define KSPLIT 16
#define NSPLIT 8
#define CHUNK 256
#define ATT_SCALE 0.08838834764831843f
#define ALO_OFF (BATCH * HIDDEN)

__device__ float g_part[KSPLIT * BATCH * NQKV];
__device__ float g_Asp[2 * BATCH * HIDDEN];   // tf32 hi at [i], lo at [ALO_OFF + i]
__device__ float g_q[BATCH * HIDDEN];
__device__ float g_kn[BATCH * NKVH * 128];
__device__ float g_vn[BATCH * NKVH * 128];
__device__ float g_pm[BATCH * NKVH * NSPLIT * 4];
__device__ float g_pl[BATCH * NKVH * NSPLIT * 4];
__device__ float g_pacc[BATCH * NKVH * NSPLIT * 4 * 128];

__device__ __forceinline__ float f2tff(float f) {
    uint32_t u; asm("cvt.rna.tf32.f32 %0, %1;" : "=r"(u) : "f"(f));
    return __uint_as_float(u);
}
__device__ __forceinline__ void mma8(float* d, const uint32_t* a, const uint32_t* b) {
    asm volatile("mma.sync.aligned.m16n8k8.row.col.f32.tf32.tf32.f32 "
        "{%0,%1,%2,%3},{%4,%5,%6,%7},{%8,%9},{%0,%1,%2,%3};"
        : "+f"(d[0]), "+f"(d[1]), "+f"(d[2]), "+f"(d[3])
        : "r"(a[0]), "r"(a[1]), "r"(a[2]), "r"(a[3]), "r"(b[0]), "r"(b[1]));
}
__device__ __forceinline__ float f4e(const float4 v, int s) {
    return s == 0 ? v.x : (s == 1 ? v.y : (s == 2 ? v.z : v.w));
}
__device__ __forceinline__ uint32_t f4u(const float4 v, int s) {
    return __float_as_uint(f4e(v, s));
}
__device__ __forceinline__ float4 tf4(float4 v) {
    return make_float4(f2tff(v.x), f2tff(v.y), f2tff(v.z), f2tff(v.w));
}

__global__ void split_a(const float* __restrict__ A) {
    int t = blockIdx.x * blockDim.x + threadIdx.x;
    if (t >= BATCH * HIDDEN) return;
    float x = A[t];
    float hi = f2tff(x);
    g_Asp[t] = hi;
    g_Asp[ALO_OFF + t] = f2tff(x - hi);
}

// R6 GEMM (known 42.6us): C[m,n] partial = sum_{k in split} A[m,k]*Bm[n,k].
__global__ __launch_bounds__(256, 2) void gemm_tf32(const float* __restrict__ Bm, int N) {
    int w = threadIdx.x >> 5, lane = threadIdx.x & 31;
    int c = lane & 3, g = lane >> 2;
    int nbase = blockIdx.x * 256 + w * 32;
    const int kper = HIDDEN / KSPLIT;
    int k0 = blockIdx.y * kper;

    float d[2][4][4];
#pragma unroll
    for (int t = 0; t < 2; t++)
#pragma unroll
        for (int j = 0; j < 4; j++)
#pragma unroll
            for (int q = 0; q < 4; q++) d[t][j][q] = 0.f;

    const float *Ap[4], *Bp[4];
#pragma unroll
    for (int r = 0; r < 4; r++) Ap[r] = g_Asp + (size_t)(g + 8 * r) * HIDDEN + c * 8;
#pragma unroll
    for (int j = 0; j < 4; j++) Bp[j] = Bm + (size_t)(nbase + 8 * j + g) * HIDDEN + c * 8;

    for (int kc = k0; kc < k0 + kper; kc += 32) {
        float4 b0[4], b1[4];
#pragma unroll
        for (int j = 0; j < 4; j++) {
            b0[j] = *(const float4*)(Bp[j] + kc);
            b1[j] = *(const float4*)(Bp[j] + kc + 4);
        }
#pragma unroll
        for (int j = 0; j < 4; j++) { b0[j] = tf4(b0[j]); b1[j] = tf4(b1[j]); }
        float4 x0[4], x1[4];
#pragma unroll
        for (int r = 0; r < 4; r++) {
            x0[r] = *(const float4*)(Ap[r] + kc);
            x1[r] = *(const float4*)(Ap[r] + kc + 4);
        }
#pragma unroll
        for (int s = 0; s < 4; s++)
#pragma unroll
            for (int t = 0; t < 2; t++) {
                uint32_t af[4] = { f4u(x0[2*t], s), f4u(x0[2*t+1], s), f4u(x1[2*t], s), f4u(x1[2*t+1], s) };
#pragma unroll
                for (int j = 0; j < 4; j++) {
                    uint32_t bf[2] = { f4u(b0[j], s), f4u(b1[j], s) };
                    mma8(d[t][j], af, bf);
                }
            }
#pragma unroll
        for (int r = 0; r < 4; r++) {
            x0[r] = *(const float4*)(Ap[r] + kc + ALO_OFF);
            x1[r] = *(const float4*)(Ap[r] + kc + 4 + ALO_OFF);
        }
#pragma unroll
        for (int s = 0; s < 4; s++)
#pragma unroll
            for (int t = 0; t < 2; t++) {
                uint32_t af[4] = { f4u(x0[2*t], s), f4u(x0[2*t+1], s), f4u(x1[2*t], s), f4u(x1[2*t+1], s) };
#pragma unroll
                for (int j = 0; j < 4; j++) {
                    uint32_t bf[2] = { f4u(b0[j], s), f4u(b1[j], s) };
                    mma8(d[t][j], af, bf);
                }
            }
    }
    float* outp = g_part + (size_t)blockIdx.y * BATCH * N;
#pragma unroll
    for (int t = 0; t < 2; t++)
#pragma unroll
        for (int j = 0; j < 4; j++) {
            int row = g + 16 * t, col = nbase + 8 * j + 2 * c;
            *(float2*)(outp + (size_t)row * N + col)       = make_float2(d[t][j][0], d[t][j][1]);
            *(float2*)(outp + (size_t)(row + 8) * N + col) = make_float2(d[t][j][2], d[t][j][3]);
        }
}

__global__ void reduce_qkv(const float* __restrict__ bias, const int* __restrict__ ctx) {
    int t = blockIdx.x * blockDim.x + threadIdx.x;
    if (t >= BATCH * NQKV) return;
    int b = t / NQKV, n = t % NQKV;
    int pos = ctx[b] - 1;
    if (n < 5120) {
        int base = (n < 4096) ? 0 : 4096;
        int loc = n - base, h = loc >> 7, dd = loc & 127;
        if (dd >= 64) return;
        float x1 = bias[n], x2 = bias[n + 64];
        for (int i = 0; i < KSPLIT; i++) {
            x1 += g_part[(size_t)i * BATCH * NQKV + b * NQKV + n];
            x2 += g_part[(size_t)i * BATCH * NQKV + b * NQKV + n + 64];
        }
        double ifr = exp(-(double)dd / 64.0 * log(10000.0));
        float ang = (float)pos * (float)ifr;
        float cs = cosf(ang), sn = sinf(ang);
        float o1 = x1 * cs - x2 * sn, o2 = x2 * cs + x1 * sn;
        if (n < 4096) {
            g_q[b * HIDDEN + h * 128 + dd]      = o1 * ATT_SCALE;
            g_q[b * HIDDEN + h * 128 + dd + 64] = o2 * ATT_SCALE;
        } else {
            g_kn[b * 1024 + h * 128 + dd]      = o1;
            g_kn[b * 1024 + h * 128 + dd + 64] = o2;
        }
    } else {
        float s = bias[n];
        for (int i = 0; i < KSPLIT; i++) s += g_part[(size_t)i * BATCH * NQKV + b * NQKV + n];
        g_vn[b * 1024 + (n - 5120)] = s;
    }
}

// Flash-decode, one warp = 128 positions in a single pass. 2 warps / 64 threads per block.
// Phase A: 32 grps x 4 K rows (full 128B line per row), scores -> smem.
// Phase B: one softmax pass over 128 positions (4 per lane).
// Phase C: one coalesced V sweep over 128 positions.
__global__ __launch_bounds__(64) void attn_split(const float* __restrict__ kc,
                                                 const float* __restrict__ vc,
                                                 const int* __restrict__ bt,
                                                 const int* __restrict__ ctx) {
    int split = blockIdx.x, kvh = blockIdx.y, b = blockIdx.z;
    int L = ctx[b];
    if (split * CHUNK >= L) return;
    int send = split * CHUNK + CHUNK; if (send > L) send = L;
    int tid = threadIdx.x, w = tid >> 5, lane = tid & 31;
    int pos = L - 1;
    int u8 = lane & 7, row = lane >> 3;   // 8 lanes per K row

    __shared__ float sq[4][128];
    __shared__ float se[2][128][4];
    __shared__ const float* svp[2][128];
    __shared__ float sm[2][4], sl[2][4];
    __shared__ float sacc[2][4][128];
    for (int i = tid; i < 512; i += 64) sq[i >> 7][i & 127] = g_q[b * HIDDEN + kvh * 512 + i];
    __syncthreads();

    const float* knrow = g_kn + (b * 8 + kvh) * 128;
    const float* vnrow = g_vn + (b * 8 + kvh) * 128;

    float m[4] = {-1e30f, -1e30f, -1e30f, -1e30f};
    float lsum[4] = {0, 0, 0, 0};
    float acc[4][4] = {};
    int p0 = split * CHUNK + w * 128;
    int nv = send - p0;
    if (nv > 128) nv = 128;
    if (nv > 0) {
        bool fast = (nv == 128) && (pos < p0 || pos >= p0 + 128);
        // ---- Phase A: scores for 128 positions, 32 grps x 4 rows ----
#pragma unroll 4
        for (int grp = 0; grp < 32; grp++) {
            int p = p0 + grp * 4 + row;
            const float *kr, *vr;
            bool pv = true;
            if (fast) {
                int blk = __ldg(bt + b * 128 + (p >> 4));
                long long off = ((long long)(blk * 16 + (p & 15)) * 8 + kvh) * 128;
                kr = kc + off; vr = vc + off;
            } else {
                pv = p < send;
                if (pv) {
                    if (p == pos) { kr = knrow; vr = vnrow; }
                    else {
                        int blk = __ldg(bt + b * 128 + (p >> 4));
                        long long off = ((long long)(blk * 16 + (p & 15)) * 8 + kvh) * 128;
                        kr = kc + off; vr = vc + off;
                    }
                } else { kr = vc; vr = vc; }
            }
            if (u8 == 0) svp[w][grp * 4 + row] = vr;
            float t0 = 0, t1 = 0, t2 = 0, t3 = 0;
#pragma unroll
            for (int j = 0; j < 4; j++) {
                int u = u8 + 8 * j;          // full 128B line per row per LDG
                float4 k4 = __ldcs((const float4*)kr + u);
                float4 q0 = ((const float4*)sq[0])[u], q1 = ((const float4*)sq[1])[u];
                float4 q2 = ((const float4*)sq[2])[u], q3 = ((const float4*)sq[3])[u];
                t0 += k4.x*q0.x + k4.y*q0.y + k4.z*q0.z + k4.w*q0.w;
                t1 += k4.x*q1.x + k4.y*q1.y + k4.z*q1.z + k4.w*q1.w;
                t2 += k4.x*q2.x + k4.y*q2.y + k4.z*q2.z + k4.w*q2.w;
                t3 += k4.x*q3.x + k4.y*q3.y + k4.z*q3.z + k4.w*q3.w;
            }
            t0 += __shfl_xor_sync(~0u, t0, 1); t0 += __shfl_xor_sync(~0u, t0, 2); t0 += __shfl_xor_sync(~0u, t0, 4);
            t1 += __shfl_xor_sync(~0u, t1, 1); t1 += __shfl_xor_sync(~0u, t1, 2); t1 += __shfl_xor_sync(~0u, t1, 4);
            t2 += __shfl_xor_sync(~0u, t2, 1); t2 += __shfl_xor_sync(~0u, t2, 2); t2 += __shfl_xor_sync(~0u, t2, 4);
            t3 += __shfl_xor_sync(~0u, t3, 1); t3 += __shfl_xor_sync(~0u, t3, 2); t3 += __shfl_xor_sync(~0u, t3, 4);
            if (u8 == 0) {
                *(float4*)se[w][grp * 4 + row] = pv ? make_float4(t0, t1, t2, t3)
                                                    : make_float4(-1e30f, -1e30f, -1e30f, -1e30f);
            }
        }
        __syncwarp();
        // ---- Phase B: one softmax pass, 4 positions per lane ----
        float4 sv0 = *(const float4*)se[w][lane];
        float4 sv1 = *(const float4*)se[w][lane + 32];
        float4 sv2 = *(const float4*)se[w][lane + 64];
        float4 sv3 = *(const float4*)se[w][lane + 96];
        float mx0 = fmaxf(fmaxf(sv0.x, sv1.x), fmaxf(sv2.x, sv3.x));
        float mx1 = fmaxf(fmaxf(sv0.y, sv1.y), fmaxf(sv2.y, sv3.y));
        float mx2 = fmaxf(fmaxf(sv0.z, sv1.z), fmaxf(sv2.z, sv3.z));
        float mx3 = fmaxf(fmaxf(sv0.w, sv1.w), fmaxf(sv2.w, sv3.w));
        for (int o = 16; o; o >>= 1) {
            mx0 = fmaxf(mx0, __shfl_xor_sync(~0u, mx0, o));
            mx1 = fmaxf(mx1, __shfl_xor_sync(~0u, mx1, o));
            mx2 = fmaxf(mx2, __shfl_xor_sync(~0u, mx2, o));
            mx3 = fmaxf(mx3, __shfl_xor_sync(~0u, mx3, o));
        }
        float mn0 = fmaxf(m[0], mx0), mn1 = fmaxf(m[1], mx1);
        float mn2 = fmaxf(m[2], mx2), mn3 = fmaxf(m[3], mx3);
        m[0] = mn0; m[1] = mn1; m[2] = mn2; m[3] = mn3;
        {
            float e0 = expf(sv0.x - mn0), e1 = expf(sv0.y - mn1);
            float e2 = expf(sv0.z - mn2), e3 = expf(sv0.w - mn3);
            lsum[0] += e0; lsum[1] += e1; lsum[2] += e2; lsum[3] += e3;
            *(float4*)se[w][lane] = make_float4(e0, e1, e2, e3);
        }
        {
            float e0 = expf(sv1.x - mn0), e1 = expf(sv1.y - mn1);
            float e2 = expf(sv1.z - mn2), e3 = expf(sv1.w - mn3);
            lsum[0] += e0; lsum[1] += e1; lsum[2] += e2; lsum[3] += e3;
            *(float4*)se[w][lane + 32] = make_float4(e0, e1, e2, e3);
        }
        {
            float e0 = expf(sv2.x - mn0), e1 = expf(sv2.y - mn1);
            float e2 = expf(sv2.z - mn2), e3 = expf(sv2.w - mn3);
            lsum[0] += e0; lsum[1] += e1; lsum[2] += e2; lsum[3] += e3;
            *(float4*)se[w][lane + 64] = make_float4(e0, e1, e2, e3);
        }
        {
            float e0 = expf(sv3.x - mn0), e1 = expf(sv3.y - mn1);
            float e2 = expf(sv3.z - mn2), e3 = expf(sv3.w - mn3);
            lsum[0] += e0; lsum[1] += e1; lsum[2] += e2; lsum[3] += e3;
            *(float4*)se[w][lane + 96] = make_float4(e0, e1, e2, e3);
        }
        __syncwarp();
        // ---- Phase C: one V sweep over 128 positions ----
        if (nv == 128) {
#pragma unroll 8
            for (int pp = 0; pp < 128; pp++) {
                float4 e4 = *(const float4*)se[w][pp];
                float4 v4 = __ldcs((const float4*)svp[w][pp] + lane);
                acc[0][0] += e4.x*v4.x; acc[0][1] += e4.x*v4.y; acc[0][2] += e4.x*v4.z; acc[0][3] += e4.x*v4.w;
                acc[1][0] += e4.y*v4.x; acc[1][1] += e4.y*v4.y; acc[1][2] += e4.y*v4.z; acc[1][3] += e4.y*v4.w;
                acc[2][0] += e4.z*v4.x; acc[2][1] += e4.z*v4.y; acc[2][2] += e4.z*v4.z; acc[2][3] += e4.z*v4.w;
                acc[3][0] += e4.w*v4.x; acc[3][1] += e4.w*v4.y; acc[3][2] += e4.w*v4.z; acc[3][3] += e4.w*v4.w;
            }
        } else {
            for (int pp = 0; pp < nv; pp++) {
                float4 e4 = *(const float4*)se[w][pp];
                float4 v4 = __ldcs((const float4*)svp[w][pp] + lane);
                acc[0][0] += e4.x*v4.x; acc[0][1] += e4.x*v4.y; acc[0][2] += e4.x*v4.z; acc[0][3] += e4.x*v4.w;
                acc[1][0] += e4.y*v4.x; acc[1][1] += e4.y*v4.y; acc[1][2] += e4.y*v4.z; acc[1][3] += e4.y*v4.w;
                acc[2][0] += e4.z*v4.x; acc[2][1] += e4.z*v4.y; acc[2][2] += e4.z*v4.z; acc[2][3] += e4.z*v4.w;
                acc[3][0] += e4.w*v4.x; acc[3][1] += e4.w*v4.y; acc[3][2] += e4.w*v4.z; acc[3][3] += e4.w*v4.w;
            }
        }
    }
#pragma unroll
    for (int h = 0; h < 4; h++) {
        float lt = lsum[h];
        for (int o = 16; o; o >>= 1) lt += __shfl_xor_sync(~0u, lt, o);
        if (lane == 0) { sm[w][h] = m[h]; sl[w][h] = lt; }
#pragma unroll
        for (int j = 0; j < 4; j++) sacc[w][h][lane * 4 + j] = acc[h][j];
    }
    __syncthreads();
    for (int h = 0; h < 4; h++) {
        float mb = fmaxf(sm[0][h], sm[1][h]);
        float lb = 0, ab0 = 0, ab1 = 0;
        float ea = expf(sm[0][h] - mb), eb = expf(sm[1][h] - mb);
        lb = ea * sl[0][h] + eb * sl[1][h];
        int idx = ((b * 8 + kvh) * NSPLIT + split) * 4 + h;
        // 64 threads cover 128 dims: each thread handles 2
        ab0 = ea * sacc[0][h][tid]      + eb * sacc[1][h][tid];
        ab1 = ea * sacc[0][h][tid + 64] + eb * sacc[1][h][tid + 64];
        if (tid == 0) { g_pm[idx] = mb; g_pl[idx] = lb; }
        g_pacc[(size_t)idx * 128 + tid]      = ab0;
        g_pacc[(size_t)idx * 128 + tid + 64] = ab1;
    }
}

// grid (NKVH, BATCH), 512 threads. Emits tf32-split A for O-GEMM.
__global__ __launch_bounds__(512) void attn_reduce(const int* __restrict__ ctx) {
    int kvh = blockIdx.x, b = blockIdx.y;
    int h = threadIdx.x >> 7, t = threadIdx.x & 127;
    int L = ctx[b];
    int nact = (L + CHUNK - 1) / CHUNK;
    if (nact > NSPLIT) nact = NSPLIT;
    int base = ((b * 8 + kvh) * NSPLIT) * 4 + h;
    float mb = -1e30f;
    for (int s = 0; s < nact; s++) mb = fmaxf(mb, g_pm[base + s * 4]);
    float lt = 0.f, a = 0.f;
    for (int s = 0; s < nact; s++) {
        int idx = base + s * 4;
        float e = expf(g_pm[idx] - mb);
        lt += e * g_pl[idx];
        a += e * g_pacc[(size_t)idx * 128 + t];
    }
    float r = a / lt;
    float hi = f2tff(r);
    int idx = b * HIDDEN + (kvh * 4 + h) * 128 + t;
    g_Asp[idx] = hi;
    g_Asp[ALO_OFF + idx] = f2tff(r - hi);
}

__global__ void reduce_out(const float* __restrict__ bias, float* __restrict__ out) {
    int t = blockIdx.x * blockDim.x + threadIdx.x;
    if (t >= BATCH * HIDDEN) return;
    int b = t / HIDDEN, n = t % HIDDEN;
    float s = bias[n];
    for (int i = 0; i < KSPLIT; i++) s += g_part[(size_t)i * BATCH * HIDDEN + b * HIDDEN + n];
    out[t] = s;
}

extern "C" void kernel_launch(void* const* d_in, const int* in_sizes, int n_in,
                              void* d_out, int out_size) {
    const float* hs = (const float*)d_in[0];
    const float* Wq = (const float*)d_in[1];
    const float* bq = (const float*)d_in[2];
    const float* Wo = (const float*)d_in[3];
    const float* bo = (const float*)d_in[4];
    const float* kc = (const float*)d_in[5];
    const float* vc = (const float*)d_in[6];
    const int*   bt = (const int*)d_in[7];
    const int*  ctx = (const int*)d_in[8];
    float* out = (float*)d_out;

    split_a<<<(BATCH * HIDDEN + 255) / 256, 256>>>(hs);
    gemm_tf32<<<dim3(NQKV / 256, KSPLIT), 256>>>(Wq, NQKV);
    reduce_qkv<<<(BATCH * NQKV + 255) / 256, 256>>>(bq, ctx);
    attn_split<<<dim3(NSPLIT, NKVH, BATCH), 64>>>(kc, vc, bt, ctx);
    attn_reduce<<<dim3(NKVH, BATCH), 512>>>(ctx);
    gemm_tf32<<<dim3(HIDDEN / 256, KSPLIT), 256>>>(Wo, HIDDEN);
    reduce_out<<<(BATCH * HIDDEN + 255) / 256, 256>>>(bo, out);
}

// round 15
// speedup vs baseline: 1.1839x; 1.1839x over previous
#include <cuda_runtime.h>
#include <cstdint>

#define BATCH 32
#define NKVH 8
#define HIDDEN 4096
#define NQKV 6144
#define KSPLIT 8
#define NSPLIT 8
#define CHUNK 256
#define ATT_SCALE 0.08838834764831843f
#define ALO_OFF (BATCH * HIDDEN)

__device__ float g_part[KSPLIT * BATCH * NQKV];
__device__ float g_Asp[2 * BATCH * HIDDEN];   // tf32 hi at [i], lo at [ALO_OFF + i]
__device__ float g_q[BATCH * HIDDEN];
__device__ float g_kn[BATCH * NKVH * 128];
__device__ float g_vn[BATCH * NKVH * 128];
__device__ float g_pm[BATCH * NKVH * NSPLIT * 4];
__device__ float g_pl[BATCH * NKVH * NSPLIT * 4];
__device__ float g_pacc[BATCH * NKVH * NSPLIT * 4 * 128];

__device__ __forceinline__ float f2tff(float f) {
    uint32_t u; asm("cvt.rna.tf32.f32 %0, %1;" : "=r"(u) : "f"(f));
    return __uint_as_float(u);
}
__device__ __forceinline__ void mma8(float* d, const uint32_t* a, const uint32_t* b) {
    asm volatile("mma.sync.aligned.m16n8k8.row.col.f32.tf32.tf32.f32 "
        "{%0,%1,%2,%3},{%4,%5,%6,%7},{%8,%9},{%0,%1,%2,%3};"
        : "+f"(d[0]), "+f"(d[1]), "+f"(d[2]), "+f"(d[3])
        : "r"(a[0]), "r"(a[1]), "r"(a[2]), "r"(a[3]), "r"(b[0]), "r"(b[1]));
}
__device__ __forceinline__ float f4e(const float4 v, int s) {
    return s == 0 ? v.x : (s == 1 ? v.y : (s == 2 ? v.z : v.w));
}
__device__ __forceinline__ uint32_t f4u(const float4 v, int s) {
    return __float_as_uint(f4e(v, s));
}
__device__ __forceinline__ float4 tf4(float4 v) {
    return make_float4(f2tff(v.x), f2tff(v.y), f2tff(v.z), f2tff(v.w));
}

__global__ void split_a(const float* __restrict__ A) {
    int t = blockIdx.x * blockDim.x + threadIdx.x;
    if (t >= BATCH * HIDDEN) return;
    float x = A[t];
    float hi = f2tff(x);
    g_Asp[t] = hi;
    g_Asp[ALO_OFF + t] = f2tff(x - hi);
}

// R6 inner loop, new launch shape: 128-thread blocks (4 warps, block tile 128 N),
// KSPLIT=8 (kper=512). grid=(N/128, 8) -> single wave at 4 blocks/SM.
__global__ __launch_bounds__(128, 4) void gemm_tf32(const float* __restrict__ Bm, int N) {
    int w = threadIdx.x >> 5, lane = threadIdx.x & 31;
    int c = lane & 3, g = lane >> 2;
    int nbase = blockIdx.x * 128 + w * 32;
    const int kper = HIDDEN / KSPLIT;
    int k0 = blockIdx.y * kper;

    float d[2][4][4];
#pragma unroll
    for (int t = 0; t < 2; t++)
#pragma unroll
        for (int j = 0; j < 4; j++)
#pragma unroll
            for (int q = 0; q < 4; q++) d[t][j][q] = 0.f;

    const float *Ap[4], *Bp[4];
#pragma unroll
    for (int r = 0; r < 4; r++) Ap[r] = g_Asp + (size_t)(g + 8 * r) * HIDDEN + c * 8;
#pragma unroll
    for (int j = 0; j < 4; j++) Bp[j] = Bm + (size_t)(nbase + 8 * j + g) * HIDDEN + c * 8;

    for (int kc = k0; kc < k0 + kper; kc += 32) {
        float4 b0[4], b1[4];
#pragma unroll
        for (int j = 0; j < 4; j++) {
            b0[j] = *(const float4*)(Bp[j] + kc);
            b1[j] = *(const float4*)(Bp[j] + kc + 4);
        }
#pragma unroll
        for (int j = 0; j < 4; j++) { b0[j] = tf4(b0[j]); b1[j] = tf4(b1[j]); }
        float4 x0[4], x1[4];
#pragma unroll
        for (int r = 0; r < 4; r++) {
            x0[r] = *(const float4*)(Ap[r] + kc);
            x1[r] = *(const float4*)(Ap[r] + kc + 4);
        }
#pragma unroll
        for (int s = 0; s < 4; s++)
#pragma unroll
            for (int t = 0; t < 2; t++) {
                uint32_t af[4] = { f4u(x0[2*t], s), f4u(x0[2*t+1], s), f4u(x1[2*t], s), f4u(x1[2*t+1], s) };
#pragma unroll
                for (int j = 0; j < 4; j++) {
                    uint32_t bf[2] = { f4u(b0[j], s), f4u(b1[j], s) };
                    mma8(d[t][j], af, bf);
                }
            }
#pragma unroll
        for (int r = 0; r < 4; r++) {
            x0[r] = *(const float4*)(Ap[r] + kc + ALO_OFF);
            x1[r] = *(const float4*)(Ap[r] + kc + 4 + ALO_OFF);
        }
#pragma unroll
        for (int s = 0; s < 4; s++)
#pragma unroll
            for (int t = 0; t < 2; t++) {
                uint32_t af[4] = { f4u(x0[2*t], s), f4u(x0[2*t+1], s), f4u(x1[2*t], s), f4u(x1[2*t+1], s) };
#pragma unroll
                for (int j = 0; j < 4; j++) {
                    uint32_t bf[2] = { f4u(b0[j], s), f4u(b1[j], s) };
                    mma8(d[t][j], af, bf);
                }
            }
    }
    float* outp = g_part + (size_t)blockIdx.y * BATCH * N;
#pragma unroll
    for (int t = 0; t < 2; t++)
#pragma unroll
        for (int j = 0; j < 4; j++) {
            int row = g + 16 * t, col = nbase + 8 * j + 2 * c;
            *(float2*)(outp + (size_t)row * N + col)       = make_float2(d[t][j][0], d[t][j][1]);
            *(float2*)(outp + (size_t)(row + 8) * N + col) = make_float2(d[t][j][2], d[t][j][3]);
        }
}

__global__ void reduce_qkv(const float* __restrict__ bias, const int* __restrict__ ctx) {
    int t = blockIdx.x * blockDim.x + threadIdx.x;
    if (t >= BATCH * NQKV) return;
    int b = t / NQKV, n = t % NQKV;
    int pos = ctx[b] - 1;
    if (n < 5120) {
        int base = (n < 4096) ? 0 : 4096;
        int loc = n - base, h = loc >> 7, dd = loc & 127;
        if (dd >= 64) return;
        float x1 = bias[n], x2 = bias[n + 64];
        for (int i = 0; i < KSPLIT; i++) {
            x1 += g_part[(size_t)i * BATCH * NQKV + b * NQKV + n];
            x2 += g_part[(size_t)i * BATCH * NQKV + b * NQKV + n + 64];
        }
        double ifr = exp(-(double)dd / 64.0 * log(10000.0));
        float ang = (float)pos * (float)ifr;
        float cs = cosf(ang), sn = sinf(ang);
        float o1 = x1 * cs - x2 * sn, o2 = x2 * cs + x1 * sn;
        if (n < 4096) {
            g_q[b * HIDDEN + h * 128 + dd]      = o1 * ATT_SCALE;
            g_q[b * HIDDEN + h * 128 + dd + 64] = o2 * ATT_SCALE;
        } else {
            g_kn[b * 1024 + h * 128 + dd]      = o1;
            g_kn[b * 1024 + h * 128 + dd + 64] = o2;
        }
    } else {
        float s = bias[n];
        for (int i = 0; i < KSPLIT; i++) s += g_part[(size_t)i * BATCH * NQKV + b * NQKV + n];
        g_vn[b * 1024 + (n - 5120)] = s;
    }
}

// R13 attn_split (known 55.5us): one 64-position pass per warp, 4 warps/128 thr.
__global__ __launch_bounds__(128) void attn_split(const float* __restrict__ kc,
                                                  const float* __restrict__ vc,
                                                  const int* __restrict__ bt,
                                                  const int* __restrict__ ctx) {
    int split = blockIdx.x, kvh = blockIdx.y, b = blockIdx.z;
    int L = ctx[b];
    if (split * CHUNK >= L) return;
    int send = split * CHUNK + CHUNK; if (send > L) send = L;
    int tid = threadIdx.x, w = tid >> 5, lane = tid & 31;
    int pos = L - 1;
    int u8 = lane & 7, row = lane >> 3;   // 8 lanes per K row

    __shared__ float sq[4][128];
    __shared__ float se[4][64][4];
    __shared__ const float* svp[4][64];
    __shared__ float sm[4][4], sl[4][4];
    __shared__ float sacc[4][4][128];
    for (int i = tid; i < 512; i += 128) sq[i >> 7][i & 127] = g_q[b * HIDDEN + kvh * 512 + i];
    __syncthreads();

    const float* knrow = g_kn + (b * 8 + kvh) * 128;
    const float* vnrow = g_vn + (b * 8 + kvh) * 128;

    float m[4] = {-1e30f, -1e30f, -1e30f, -1e30f};
    float lsum[4] = {0, 0, 0, 0};
    float acc[4][4] = {};
    int p0 = split * CHUNK + w * 64;
    int nv = send - p0;
    if (nv > 64) nv = 64;
    if (nv > 0) {
        bool fast = (nv == 64) && (pos < p0 || pos >= p0 + 64);
        // ---- Phase A: scores for 64 positions, 16 grps x 4 rows ----
#pragma unroll 4
        for (int grp = 0; grp < 16; grp++) {
            int p = p0 + grp * 4 + row;
            const float *kr, *vr;
            bool pv = true;
            if (fast) {
                int blk = __ldg(bt + b * 128 + (p >> 4));
                long long off = ((long long)(blk * 16 + (p & 15)) * 8 + kvh) * 128;
                kr = kc + off; vr = vc + off;
            } else {
                pv = p < send;
                if (pv) {
                    if (p == pos) { kr = knrow; vr = vnrow; }
                    else {
                        int blk = __ldg(bt + b * 128 + (p >> 4));
                        long long off = ((long long)(blk * 16 + (p & 15)) * 8 + kvh) * 128;
                        kr = kc + off; vr = vc + off;
                    }
                } else { kr = vc; vr = vc; }
            }
            if (u8 == 0) svp[w][grp * 4 + row] = vr;
            float t0 = 0, t1 = 0, t2 = 0, t3 = 0;
#pragma unroll
            for (int j = 0; j < 4; j++) {
                int u = u8 + 8 * j;          // full 128B line per row per LDG
                float4 k4 = __ldcs((const float4*)kr + u);
                float4 q0 = ((const float4*)sq[0])[u], q1 = ((const float4*)sq[1])[u];
                float4 q2 = ((const float4*)sq[2])[u], q3 = ((const float4*)sq[3])[u];
                t0 += k4.x*q0.x + k4.y*q0.y + k4.z*q0.z + k4.w*q0.w;
                t1 += k4.x*q1.x + k4.y*q1.y + k4.z*q1.z + k4.w*q1.w;
                t2 += k4.x*q2.x + k4.y*q2.y + k4.z*q2.z + k4.w*q2.w;
                t3 += k4.x*q3.x + k4.y*q3.y + k4.z*q3.z + k4.w*q3.w;
            }
            t0 += __shfl_xor_sync(~0u, t0, 1); t0 += __shfl_xor_sync(~0u, t0, 2); t0 += __shfl_xor_sync(~0u, t0, 4);
            t1 += __shfl_xor_sync(~0u, t1, 1); t1 += __shfl_xor_sync(~0u, t1, 2); t1 += __shfl_xor_sync(~0u, t1, 4);
            t2 += __shfl_xor_sync(~0u, t2, 1); t2 += __shfl_xor_sync(~0u, t2, 2); t2 += __shfl_xor_sync(~0u, t2, 4);
            t3 += __shfl_xor_sync(~0u, t3, 1); t3 += __shfl_xor_sync(~0u, t3, 2); t3 += __shfl_xor_sync(~0u, t3, 4);
            if (u8 == 0) {
                *(float4*)se[w][grp * 4 + row] = pv ? make_float4(t0, t1, t2, t3)
                                                    : make_float4(-1e30f, -1e30f, -1e30f, -1e30f);
            }
        }
        __syncwarp();
        // ---- Phase B: one softmax pass, 2 positions per lane ----
        float4 sv0 = *(const float4*)se[w][lane];
        float4 sv1 = *(const float4*)se[w][lane + 32];
        float mx0 = fmaxf(sv0.x, sv1.x), mx1 = fmaxf(sv0.y, sv1.y);
        float mx2 = fmaxf(sv0.z, sv1.z), mx3 = fmaxf(sv0.w, sv1.w);
        for (int o = 16; o; o >>= 1) {
            mx0 = fmaxf(mx0, __shfl_xor_sync(~0u, mx0, o));
            mx1 = fmaxf(mx1, __shfl_xor_sync(~0u, mx1, o));
            mx2 = fmaxf(mx2, __shfl_xor_sync(~0u, mx2, o));
            mx3 = fmaxf(mx3, __shfl_xor_sync(~0u, mx3, o));
        }
        float mn0 = fmaxf(m[0], mx0), mn1 = fmaxf(m[1], mx1);
        float mn2 = fmaxf(m[2], mx2), mn3 = fmaxf(m[3], mx3);
        m[0] = mn0; m[1] = mn1; m[2] = mn2; m[3] = mn3;
        float e00 = expf(sv0.x - mn0), e01 = expf(sv0.y - mn1);
        float e02 = expf(sv0.z - mn2), e03 = expf(sv0.w - mn3);
        float e10 = expf(sv1.x - mn0), e11 = expf(sv1.y - mn1);
        float e12 = expf(sv1.z - mn2), e13 = expf(sv1.w - mn3);
        lsum[0] += e00 + e10; lsum[1] += e01 + e11;
        lsum[2] += e02 + e12; lsum[3] += e03 + e13;
        *(float4*)se[w][lane]      = make_float4(e00, e01, e02, e03);
        *(float4*)se[w][lane + 32] = make_float4(e10, e11, e12, e13);
        __syncwarp();
        // ---- Phase C: one V sweep over 64 positions ----
        if (nv == 64) {
#pragma unroll 8
            for (int pp = 0; pp < 64; pp++) {
                float4 e4 = *(const float4*)se[w][pp];
                float4 v4 = __ldcs((const float4*)svp[w][pp] + lane);
                acc[0][0] += e4.x*v4.x; acc[0][1] += e4.x*v4.y; acc[0][2] += e4.x*v4.z; acc[0][3] += e4.x*v4.w;
                acc[1][0] += e4.y*v4.x; acc[1][1] += e4.y*v4.y; acc[1][2] += e4.y*v4.z; acc[1][3] += e4.y*v4.w;
                acc[2][0] += e4.z*v4.x; acc[2][1] += e4.z*v4.y; acc[2][2] += e4.z*v4.z; acc[2][3] += e4.z*v4.w;
                acc[3][0] += e4.w*v4.x; acc[3][1] += e4.w*v4.y; acc[3][2] += e4.w*v4.z; acc[3][3] += e4.w*v4.w;
            }
        } else {
            for (int pp = 0; pp < nv; pp++) {
                float4 e4 = *(const float4*)se[w][pp];
                float4 v4 = __ldcs((const float4*)svp[w][pp] + lane);
                acc[0][0] += e4.x*v4.x; acc[0][1] += e4.x*v4.y; acc[0][2] += e4.x*v4.z; acc[0][3] += e4.x*v4.w;
                acc[1][0] += e4.y*v4.x; acc[1][1] += e4.y*v4.y; acc[1][2] += e4.y*v4.z; acc[1][3] += e4.y*v4.w;
                acc[2][0] += e4.z*v4.x; acc[2][1] += e4.z*v4.y; acc[2][2] += e4.z*v4.z; acc[2][3] += e4.z*v4.w;
                acc[3][0] += e4.w*v4.x; acc[3][1] += e4.w*v4.y; acc[3][2] += e4.w*v4.z; acc[3][3] += e4.w*v4.w;
            }
        }
    }
#pragma unroll
    for (int h = 0; h < 4; h++) {
        float lt = lsum[h];
        for (int o = 16; o; o >>= 1) lt += __shfl_xor_sync(~0u, lt, o);
        if (lane == 0) { sm[w][h] = m[h]; sl[w][h] = lt; }
#pragma unroll
        for (int j = 0; j < 4; j++) sacc[w][h][lane * 4 + j] = acc[h][j];
    }
    __syncthreads();
    for (int h = 0; h < 4; h++) {
        float mb = fmaxf(fmaxf(sm[0][h], sm[1][h]), fmaxf(sm[2][h], sm[3][h]));
        float lb = 0, ab = 0;
        for (int ww = 0; ww < 4; ww++) {
            float e = expf(sm[ww][h] - mb);
            lb += e * sl[ww][h];
            ab += e * sacc[ww][h][tid];
        }
        int idx = ((b * 8 + kvh) * NSPLIT + split) * 4 + h;
        if (tid == 0) { g_pm[idx] = mb; g_pl[idx] = lb; }
        g_pacc[(size_t)idx * 128 + tid] = ab;
    }
}

// grid (NKVH, BATCH), 512 threads. Emits tf32-split A for O-GEMM.
__global__ __launch_bounds__(512) void attn_reduce(const int* __restrict__ ctx) {
    int kvh = blockIdx.x, b = blockIdx.y;
    int h = threadIdx.x >> 7, t = threadIdx.x & 127;
    int L = ctx[b];
    int nact = (L + CHUNK - 1) / CHUNK;
    if (nact > NSPLIT) nact = NSPLIT;
    int base = ((b * 8 + kvh) * NSPLIT) * 4 + h;
    float mb = -1e30f;
    for (int s = 0; s < nact; s++) mb = fmaxf(mb, g_pm[base + s * 4]);
    float lt = 0.f, a = 0.f;
    for (int s = 0; s < nact; s++) {
        int idx = base + s * 4;
        float e = expf(g_pm[idx] - mb);
        lt += e * g_pl[idx];
        a += e * g_pacc[(size_t)idx * 128 + t];
    }
    float r = a / lt;
    float hi = f2tff(r);
    int idx = b * HIDDEN + (kvh * 4 + h) * 128 + t;
    g_Asp[idx] = hi;
    g_Asp[ALO_OFF + idx] = f2tff(r - hi);
}

__global__ void reduce_out(const float* __restrict__ bias, float* __restrict__ out) {
    int t = blockIdx.x * blockDim.x + threadIdx.x;
    if (t >= BATCH * HIDDEN) return;
    int b = t / HIDDEN, n = t % HIDDEN;
    float s = bias[n];
    for (int i = 0; i < KSPLIT; i++) s += g_part[(size_t)i * BATCH * HIDDEN + b * HIDDEN + n];
    out[t] = s;
}

extern "C" void kernel_launch(void* const* d_in, const int* in_sizes, int n_in,
                              void* d_out, int out_size) {
    const float* hs = (const float*)d_in[0];
    const float* Wq = (const float*)d_in[1];
    const float* bq = (const float*)d_in[2];
    const float* Wo = (const float*)d_in[3];
    const float* bo = (const float*)d_in[4];
    const float* kc = (const float*)d_in[5];
    const float* vc = (const float*)d_in[6];
    const int*   bt = (const int*)d_in[7];
    const int*  ctx = (const int*)d_in[8];
    float* out = (float*)d_out;

    split_a<<<(BATCH * HIDDEN + 255) / 256, 256>>>(hs);
    gemm_tf32<<<dim3(NQKV / 128, KSPLIT), 128>>>(Wq, NQKV);
    reduce_qkv<<<(BATCH * NQKV + 255) / 256, 256>>>(bq, ctx);
    attn_split<<<dim3(NSPLIT, NKVH, BATCH), 128>>>(kc, vc, bt, ctx);
    attn_reduce<<<dim3(NKVH, BATCH), 512>>>(ctx);
    gemm_tf32<<<dim3(HIDDEN / 128, KSPLIT), 128>>>(Wo, HIDDEN);
    reduce_out<<<(BATCH * HIDDEN + 255) / 256, 256>>>(bo, out);
}

// round 16
// speedup vs baseline: 1.2926x; 1.0918x over previous
#include <cuda_runtime.h>
#include <cstdint>

#define BATCH 32
#define NKVH 8
#define HIDDEN 4096
#define NQKV 6144
#define KSPLIT 16
#define NSPLIT 8
#define CHUNK 256
#define ATT_SCALE 0.08838834764831843f

__device__ float g_part[KSPLIT * BATCH * NQKV];
__device__ float g_A[BATCH * HIDDEN];         // tf32-rounded activations
__device__ float g_q[BATCH * HIDDEN];
__device__ float g_kn[BATCH * NKVH * 128];
__device__ float g_vn[BATCH * NKVH * 128];
__device__ float g_pm[BATCH * NKVH * NSPLIT * 4];
__device__ float g_pl[BATCH * NKVH * NSPLIT * 4];
__device__ float g_pacc[BATCH * NKVH * NSPLIT * 4 * 128];

__device__ __forceinline__ float f2tff(float f) {
    uint32_t u; asm("cvt.rna.tf32.f32 %0, %1;" : "=r"(u) : "f"(f));
    return __uint_as_float(u);
}
__device__ __forceinline__ void mma8(float* d, const uint32_t* a, const uint32_t* b) {
    asm volatile("mma.sync.aligned.m16n8k8.row.col.f32.tf32.tf32.f32 "
        "{%0,%1,%2,%3},{%4,%5,%6,%7},{%8,%9},{%0,%1,%2,%3};"
        : "+f"(d[0]), "+f"(d[1]), "+f"(d[2]), "+f"(d[3])
        : "r"(a[0]), "r"(a[1]), "r"(a[2]), "r"(a[3]), "r"(b[0]), "r"(b[1]));
}
__device__ __forceinline__ float f4e(const float4 v, int s) {
    return s == 0 ? v.x : (s == 1 ? v.y : (s == 2 ? v.z : v.w));
}
__device__ __forceinline__ uint32_t f4u(const float4 v, int s) {
    return __float_as_uint(f4e(v, s));
}
__device__ __forceinline__ float4 tf4(float4 v) {
    return make_float4(f2tff(v.x), f2tff(v.y), f2tff(v.z), f2tff(v.w));
}

__global__ void split_a(const float* __restrict__ A) {
    int t = blockIdx.x * blockDim.x + threadIdx.x;
    if (t >= BATCH * HIDDEN) return;
    g_A[t] = f2tff(A[t]);
}

// R6 launch shape (256 thr, KSPLIT=16, 2 blocks/SM), single-pass tf32 A.
// C[m,n] partial = sum_{k in split} A[m,k]*Bm[n,k].
__global__ __launch_bounds__(256, 2) void gemm_tf32(const float* __restrict__ Bm, int N) {
    int w = threadIdx.x >> 5, lane = threadIdx.x & 31;
    int c = lane & 3, g = lane >> 2;
    int nbase = blockIdx.x * 256 + w * 32;
    const int kper = HIDDEN / KSPLIT;
    int k0 = blockIdx.y * kper;

    float d[2][4][4];
#pragma unroll
    for (int t = 0; t < 2; t++)
#pragma unroll
        for (int j = 0; j < 4; j++)
#pragma unroll
            for (int q = 0; q < 4; q++) d[t][j][q] = 0.f;

    const float *Ap[4], *Bp[4];
#pragma unroll
    for (int r = 0; r < 4; r++) Ap[r] = g_A + (size_t)(g + 8 * r) * HIDDEN + c * 8;
#pragma unroll
    for (int j = 0; j < 4; j++) Bp[j] = Bm + (size_t)(nbase + 8 * j + g) * HIDDEN + c * 8;

    for (int kc = k0; kc < k0 + kper; kc += 32) {
        float4 b0[4], b1[4];
#pragma unroll
        for (int j = 0; j < 4; j++) {
            b0[j] = *(const float4*)(Bp[j] + kc);
            b1[j] = *(const float4*)(Bp[j] + kc + 4);
        }
#pragma unroll
        for (int j = 0; j < 4; j++) { b0[j] = tf4(b0[j]); b1[j] = tf4(b1[j]); }
        float4 x0[4], x1[4];
#pragma unroll
        for (int r = 0; r < 4; r++) {
            x0[r] = *(const float4*)(Ap[r] + kc);
            x1[r] = *(const float4*)(Ap[r] + kc + 4);
        }
#pragma unroll
        for (int s = 0; s < 4; s++)
#pragma unroll
            for (int t = 0; t < 2; t++) {
                uint32_t af[4] = { f4u(x0[2*t], s), f4u(x0[2*t+1], s), f4u(x1[2*t], s), f4u(x1[2*t+1], s) };
#pragma unroll
                for (int j = 0; j < 4; j++) {
                    uint32_t bf[2] = { f4u(b0[j], s), f4u(b1[j], s) };
                    mma8(d[t][j], af, bf);
                }
            }
    }
    float* outp = g_part + (size_t)blockIdx.y * BATCH * N;
#pragma unroll
    for (int t = 0; t < 2; t++)
#pragma unroll
        for (int j = 0; j < 4; j++) {
            int row = g + 16 * t, col = nbase + 8 * j + 2 * c;
            *(float2*)(outp + (size_t)row * N + col)       = make_float2(d[t][j][0], d[t][j][1]);
            *(float2*)(outp + (size_t)(row + 8) * N + col) = make_float2(d[t][j][2], d[t][j][3]);
        }
}

__global__ void reduce_qkv(const float* __restrict__ bias, const int* __restrict__ ctx) {
    int t = blockIdx.x * blockDim.x + threadIdx.x;
    if (t >= BATCH * NQKV) return;
    int b = t / NQKV, n = t % NQKV;
    int pos = ctx[b] - 1;
    if (n < 5120) {
        int base = (n < 4096) ? 0 : 4096;
        int loc = n - base, h = loc >> 7, dd = loc & 127;
        if (dd >= 64) return;
        float x1 = bias[n], x2 = bias[n + 64];
        for (int i = 0; i < KSPLIT; i++) {
            x1 += g_part[(size_t)i * BATCH * NQKV + b * NQKV + n];
            x2 += g_part[(size_t)i * BATCH * NQKV + b * NQKV + n + 64];
        }
        double ifr = exp(-(double)dd / 64.0 * log(10000.0));
        float ang = (float)pos * (float)ifr;
        float cs = cosf(ang), sn = sinf(ang);
        float o1 = x1 * cs - x2 * sn, o2 = x2 * cs + x1 * sn;
        if (n < 4096) {
            g_q[b * HIDDEN + h * 128 + dd]      = o1 * ATT_SCALE;
            g_q[b * HIDDEN + h * 128 + dd + 64] = o2 * ATT_SCALE;
        } else {
            g_kn[b * 1024 + h * 128 + dd]      = o1;
            g_kn[b * 1024 + h * 128 + dd + 64] = o2;
        }
    } else {
        float s = bias[n];
        for (int i = 0; i < KSPLIT; i++) s += g_part[(size_t)i * BATCH * NQKV + b * NQKV + n];
        g_vn[b * 1024 + (n - 5120)] = s;
    }
}

// R13 attn_split (known ~54-55.5us): one 64-position pass per warp, 4 warps/128 thr.
__global__ __launch_bounds__(128) void attn_split(const float* __restrict__ kc,
                                                  const float* __restrict__ vc,
                                                  const int* __restrict__ bt,
                                                  const int* __restrict__ ctx) {
    int split = blockIdx.x, kvh = blockIdx.y, b = blockIdx.z;
    int L = ctx[b];
    if (split * CHUNK >= L) return;
    int send = split * CHUNK + CHUNK; if (send > L) send = L;
    int tid = threadIdx.x, w = tid >> 5, lane = tid & 31;
    int pos = L - 1;
    int u8 = lane & 7, row = lane >> 3;   // 8 lanes per K row

    __shared__ float sq[4][128];
    __shared__ float se[4][64][4];
    __shared__ const float* svp[4][64];
    __shared__ float sm[4][4], sl[4][4];
    __shared__ float sacc[4][4][128];
    for (int i = tid; i < 512; i += 128) sq[i >> 7][i & 127] = g_q[b * HIDDEN + kvh * 512 + i];
    __syncthreads();

    const float* knrow = g_kn + (b * 8 + kvh) * 128;
    const float* vnrow = g_vn + (b * 8 + kvh) * 128;

    float m[4] = {-1e30f, -1e30f, -1e30f, -1e30f};
    float lsum[4] = {0, 0, 0, 0};
    float acc[4][4] = {};
    int p0 = split * CHUNK + w * 64;
    int nv = send - p0;
    if (nv > 64) nv = 64;
    if (nv > 0) {
        bool fast = (nv == 64) && (pos < p0 || pos >= p0 + 64);
        // ---- Phase A: scores for 64 positions, 16 grps x 4 rows ----
#pragma unroll 4
        for (int grp = 0; grp < 16; grp++) {
            int p = p0 + grp * 4 + row;
            const float *kr, *vr;
            bool pv = true;
            if (fast) {
                int blk = __ldg(bt + b * 128 + (p >> 4));
                long long off = ((long long)(blk * 16 + (p & 15)) * 8 + kvh) * 128;
                kr = kc + off; vr = vc + off;
            } else {
                pv = p < send;
                if (pv) {
                    if (p == pos) { kr = knrow; vr = vnrow; }
                    else {
                        int blk = __ldg(bt + b * 128 + (p >> 4));
                        long long off = ((long long)(blk * 16 + (p & 15)) * 8 + kvh) * 128;
                        kr = kc + off; vr = vc + off;
                    }
                } else { kr = vc; vr = vc; }
            }
            if (u8 == 0) svp[w][grp * 4 + row] = vr;
            float t0 = 0, t1 = 0, t2 = 0, t3 = 0;
#pragma unroll
            for (int j = 0; j < 4; j++) {
                int u = u8 + 8 * j;          // full 128B line per row per LDG
                float4 k4 = __ldcs((const float4*)kr + u);
                float4 q0 = ((const float4*)sq[0])[u], q1 = ((const float4*)sq[1])[u];
                float4 q2 = ((const float4*)sq[2])[u], q3 = ((const float4*)sq[3])[u];
                t0 += k4.x*q0.x + k4.y*q0.y + k4.z*q0.z + k4.w*q0.w;
                t1 += k4.x*q1.x + k4.y*q1.y + k4.z*q1.z + k4.w*q1.w;
                t2 += k4.x*q2.x + k4.y*q2.y + k4.z*q2.z + k4.w*q2.w;
                t3 += k4.x*q3.x + k4.y*q3.y + k4.z*q3.z + k4.w*q3.w;
            }
            t0 += __shfl_xor_sync(~0u, t0, 1); t0 += __shfl_xor_sync(~0u, t0, 2); t0 += __shfl_xor_sync(~0u, t0, 4);
            t1 += __shfl_xor_sync(~0u, t1, 1); t1 += __shfl_xor_sync(~0u, t1, 2); t1 += __shfl_xor_sync(~0u, t1, 4);
            t2 += __shfl_xor_sync(~0u, t2, 1); t2 += __shfl_xor_sync(~0u, t2, 2); t2 += __shfl_xor_sync(~0u, t2, 4);
            t3 += __shfl_xor_sync(~0u, t3, 1); t3 += __shfl_xor_sync(~0u, t3, 2); t3 += __shfl_xor_sync(~0u, t3, 4);
            if (u8 == 0) {
                *(float4*)se[w][grp * 4 + row] = pv ? make_float4(t0, t1, t2, t3)
                                                    : make_float4(-1e30f, -1e30f, -1e30f, -1e30f);
            }
        }
        __syncwarp();
        // ---- Phase B: one softmax pass, 2 positions per lane ----
        float4 sv0 = *(const float4*)se[w][lane];
        float4 sv1 = *(const float4*)se[w][lane + 32];
        float mx0 = fmaxf(sv0.x, sv1.x), mx1 = fmaxf(sv0.y, sv1.y);
        float mx2 = fmaxf(sv0.z, sv1.z), mx3 = fmaxf(sv0.w, sv1.w);
        for (int o = 16; o; o >>= 1) {
            mx0 = fmaxf(mx0, __shfl_xor_sync(~0u, mx0, o));
            mx1 = fmaxf(mx1, __shfl_xor_sync(~0u, mx1, o));
            mx2 = fmaxf(mx2, __shfl_xor_sync(~0u, mx2, o));
            mx3 = fmaxf(mx3, __shfl_xor_sync(~0u, mx3, o));
        }
        float mn0 = fmaxf(m[0], mx0), mn1 = fmaxf(m[1], mx1);
        float mn2 = fmaxf(m[2], mx2), mn3 = fmaxf(m[3], mx3);
        m[0] = mn0; m[1] = mn1; m[2] = mn2; m[3] = mn3;
        float e00 = expf(sv0.x - mn0), e01 = expf(sv0.y - mn1);
        float e02 = expf(sv0.z - mn2), e03 = expf(sv0.w - mn3);
        float e10 = expf(sv1.x - mn0), e11 = expf(sv1.y - mn1);
        float e12 = expf(sv1.z - mn2), e13 = expf(sv1.w - mn3);
        lsum[0] += e00 + e10; lsum[1] += e01 + e11;
        lsum[2] += e02 + e12; lsum[3] += e03 + e13;
        *(float4*)se[w][lane]      = make_float4(e00, e01, e02, e03);
        *(float4*)se[w][lane + 32] = make_float4(e10, e11, e12, e13);
        __syncwarp();
        // ---- Phase C: one V sweep over 64 positions ----
        if (nv == 64) {
#pragma unroll 8
            for (int pp = 0; pp < 64; pp++) {
                float4 e4 = *(const float4*)se[w][pp];
                float4 v4 = __ldcs((const float4*)svp[w][pp] + lane);
                acc[0][0] += e4.x*v4.x; acc[0][1] += e4.x*v4.y; acc[0][2] += e4.x*v4.z; acc[0][3] += e4.x*v4.w;
                acc[1][0] += e4.y*v4.x; acc[1][1] += e4.y*v4.y; acc[1][2] += e4.y*v4.z; acc[1][3] += e4.y*v4.w;
                acc[2][0] += e4.z*v4.x; acc[2][1] += e4.z*v4.y; acc[2][2] += e4.z*v4.z; acc[2][3] += e4.z*v4.w;
                acc[3][0] += e4.w*v4.x; acc[3][1] += e4.w*v4.y; acc[3][2] += e4.w*v4.z; acc[3][3] += e4.w*v4.w;
            }
        } else {
            for (int pp = 0; pp < nv; pp++) {
                float4 e4 = *(const float4*)se[w][pp];
                float4 v4 = __ldcs((const float4*)svp[w][pp] + lane);
                acc[0][0] += e4.x*v4.x; acc[0][1] += e4.x*v4.y; acc[0][2] += e4.x*v4.z; acc[0][3] += e4.x*v4.w;
                acc[1][0] += e4.y*v4.x; acc[1][1] += e4.y*v4.y; acc[1][2] += e4.y*v4.z; acc[1][3] += e4.y*v4.w;
                acc[2][0] += e4.z*v4.x; acc[2][1] += e4.z*v4.y; acc[2][2] += e4.z*v4.z; acc[2][3] += e4.z*v4.w;
                acc[3][0] += e4.w*v4.x; acc[3][1] += e4.w*v4.y; acc[3][2] += e4.w*v4.z; acc[3][3] += e4.w*v4.w;
            }
        }
    }
#pragma unroll
    for (int h = 0; h < 4; h++) {
        float lt = lsum[h];
        for (int o = 16; o; o >>= 1) lt += __shfl_xor_sync(~0u, lt, o);
        if (lane == 0) { sm[w][h] = m[h]; sl[w][h] = lt; }
#pragma unroll
        for (int j = 0; j < 4; j++) sacc[w][h][lane * 4 + j] = acc[h][j];
    }
    __syncthreads();
    for (int h = 0; h < 4; h++) {
        float mb = fmaxf(fmaxf(sm[0][h], sm[1][h]), fmaxf(sm[2][h], sm[3][h]));
        float lb = 0, ab = 0;
        for (int ww = 0; ww < 4; ww++) {
            float e = expf(sm[ww][h] - mb);
            lb += e * sl[ww][h];
            ab += e * sacc[ww][h][tid];
        }
        int idx = ((b * 8 + kvh) * NSPLIT + split) * 4 + h;
        if (tid == 0) { g_pm[idx] = mb; g_pl[idx] = lb; }
        g_pacc[(size_t)idx * 128 + tid] = ab;
    }
}

// grid (NKVH, BATCH), 512 threads. Emits tf32-rounded A for O-GEMM.
__global__ __launch_bounds__(512) void attn_reduce(const int* __restrict__ ctx) {
    int kvh = blockIdx.x, b = blockIdx.y;
    int h = threadIdx.x >> 7, t = threadIdx.x & 127;
    int L = ctx[b];
    int nact = (L + CHUNK - 1) / CHUNK;
    if (nact > NSPLIT) nact = NSPLIT;
    int base = ((b * 8 + kvh) * NSPLIT) * 4 + h;
    float mb = -1e30f;
    for (int s = 0; s < nact; s++) mb = fmaxf(mb, g_pm[base + s * 4]);
    float lt = 0.f, a = 0.f;
    for (int s = 0; s < nact; s++) {
        int idx = base + s * 4;
        float e = expf(g_pm[idx] - mb);
        lt += e * g_pl[idx];
        a += e * g_pacc[(size_t)idx * 128 + t];
    }
    g_A[b * HIDDEN + (kvh * 4 + h) * 128 + t] = f2tff(a / lt);
}

__global__ void reduce_out(const float* __restrict__ bias, float* __restrict__ out) {
    int t = blockIdx.x * blockDim.x + threadIdx.x;
    if (t >= BATCH * HIDDEN) return;
    int b = t / HIDDEN, n = t % HIDDEN;
    float s = bias[n];
    for (int i = 0; i < KSPLIT; i++) s += g_part[(size_t)i * BATCH * HIDDEN + b * HIDDEN + n];
    out[t] = s;
}

extern "C" void kernel_launch(void* const* d_in, const int* in_sizes, int n_in,
                              void* d_out, int out_size) {
    const float* hs = (const float*)d_in[0];
    const float* Wq = (const float*)d_in[1];
    const float* bq = (const float*)d_in[2];
    const float* Wo = (const float*)d_in[3];
    const float* bo = (const float*)d_in[4];
    const float* kc = (const float*)d_in[5];
    const float* vc = (const float*)d_in[6];
    const int*   bt = (const int*)d_in[7];
    const int*  ctx = (const int*)d_in[8];
    float* out = (float*)d_out;

    split_a<<<(BATCH * HIDDEN + 255) / 256, 256>>>(hs);
    gemm_tf32<<<dim3(NQKV / 256, KSPLIT), 256>>>(Wq, NQKV);
    reduce_qkv<<<(BATCH * NQKV + 255) / 256, 256>>>(bq, ctx);
    attn_split<<<dim3(NSPLIT, NKVH, BATCH), 128>>>(kc, vc, bt, ctx);
    attn_reduce<<<dim3(NKVH, BATCH), 512>>>(ctx);
    gemm_tf32<<<dim3(HIDDEN / 256, KSPLIT), 256>>>(Wo, HIDDEN);
    reduce_out<<<(BATCH * HIDDEN + 255) / 256, 256>>>(bo, out);
}